// round 7
// baseline (speedup 1.0000x reference)
#include <cuda_runtime.h>
#include <cstdint>

// Problem constants
#define BB   2
#define TT   2048
#define DD   1024
#define HH   16
#define HDD  64
#define MROWS (BB * TT)   // 4096

// Device scratch (no runtime allocation allowed)
__device__ float g_q[BB * HH * TT * HDD];     // [B,H,T,HD], tf32-rounded
__device__ float g_k[BB * HH * TT * HDD];
__device__ float g_v[BB * HH * TT * HDD];
__device__ float g_att[BB * TT * DD];         // [B,T,DIM], tf32-rounded
__device__ float g_xt[MROWS * DD];            // x, tf32-rounded
__device__ float g_wqt[DD * DD];              // weights, tf32-rounded
__device__ float g_wkt[DD * DD];
__device__ float g_wvt[DD * DD];
__device__ float g_wot[DD * DD];

// ---------------------------------------------------------------------------
// helpers
// ---------------------------------------------------------------------------
__device__ __forceinline__ uint32_t f2tf32(float f) {
    uint32_t r;
    asm("cvt.rna.tf32.f32 %0, %1;" : "=r"(r) : "f"(f));
    return r;
}

__device__ __forceinline__ void mma_tf32(float* c, const uint32_t* a, const uint32_t* b) {
    asm volatile(
        "mma.sync.aligned.m16n8k8.row.col.f32.tf32.tf32.f32 "
        "{%0,%1,%2,%3}, {%4,%5,%6,%7}, {%8,%9}, {%0,%1,%2,%3};"
        : "+f"(c[0]), "+f"(c[1]), "+f"(c[2]), "+f"(c[3])
        : "r"(a[0]), "r"(a[1]), "r"(a[2]), "r"(a[3]), "r"(b[0]), "r"(b[1]));
}

__device__ __forceinline__ uint32_t sptr(const void* p) {
    return (uint32_t)__cvta_generic_to_shared(p);
}

__device__ __forceinline__ void ldsm_x4(uint32_t* r, uint32_t addr) {
    asm volatile("ldmatrix.sync.aligned.m8n8.x4.shared.b16 {%0,%1,%2,%3}, [%4];"
                 : "=r"(r[0]), "=r"(r[1]), "=r"(r[2]), "=r"(r[3]) : "r"(addr));
}

__device__ __forceinline__ void cpa16(uint32_t dst, const float* src) {
    asm volatile("cp.async.ca.shared.global [%0], [%1], 16;" :: "r"(dst), "l"(src));
}
__device__ __forceinline__ void cp_commit() {
    asm volatile("cp.async.commit_group;");
}
template <int N>
__device__ __forceinline__ void cp_wait() {
    asm volatile("cp.async.wait_group %0;" :: "n"(N));
}

// ---------------------------------------------------------------------------
// tf32 rounding pre-pass (memory bound)
// ---------------------------------------------------------------------------
__global__ void __launch_bounds__(256)
tf32_round_kernel(const float4* __restrict__ in, float4* __restrict__ out, int n4)
{
    int i = blockIdx.x * blockDim.x + threadIdx.x;
    if (i < n4) {
        float4 v = in[i];
        float4 r;
        r.x = __uint_as_float(f2tf32(v.x));
        r.y = __uint_as_float(f2tf32(v.y));
        r.z = __uint_as_float(f2tf32(v.z));
        r.w = __uint_as_float(f2tf32(v.w));
        out[i] = r;
    }
}

// ---------------------------------------------------------------------------
// Tensor-core NT GEMM, inputs pre-rounded to tf32.
// out[m,n] = sum_k A[m,k]*W[n,k]. CTA 128x128, BK=32, 256 thr, warp 32x64.
// cp.async double-buffered smem; mainloop = ldmatrix + mma only.
// QKV==1: scatter into [B,H,T,HD] with tf32 rounding.
// ---------------------------------------------------------------------------
#define SA 36                       // words per row (144 B)
#define ABYTES (128 * SA * 4)       // 18432 B per stage block
#define GEMM_SMEM (4 * ABYTES)      // 73728 B (A0,A1,B0,B1)

template <int QKV>
__device__ __forceinline__ void gemm_tc_body(const float* __restrict__ A,
                                             const float* __restrict__ W,
                                             float* __restrict__ dst)
{
    extern __shared__ __align__(16) uint32_t smg[];
    const uint32_t sbase = sptr(smg);

    const int tid    = threadIdx.x;
    const int lane   = tid & 31;
    const int wid    = tid >> 5;
    const int warp_m = wid & 3;
    const int warp_n = wid >> 2;
    const int g      = lane >> 2;
    const int t4     = lane & 3;
    const int i8     = lane >> 3;
    const int rr     = lane & 7;

    const int m0 = blockIdx.y * 128;
    const int n0 = blockIdx.x * 128;

    const int lr = tid >> 3;           // 0..31
    const int lc = (tid & 7) << 2;     // 0..28

    // relative ldmatrix offsets (bytes within a stage block; B adds 2*ABYTES)
    uint32_t aRel[2], bRel[4];
#pragma unroll
    for (int mt = 0; mt < 2; ++mt)
        aRel[mt] = ((warp_m * 32 + mt * 16 + (i8 & 1) * 8 + rr) * SA + (i8 >> 1) * 4) << 2;
#pragma unroll
    for (int p = 0; p < 4; ++p)
        bRel[p] = (uint32_t)(2 * ABYTES) +
                  (((warp_n * 64 + (2 * p + (i8 >> 1)) * 8 + rr) * SA + (i8 & 1) * 4) << 2);

    // cp.async destination offsets (per thread, 4 A rows + 4 B rows)
    uint32_t dstRel[4];
#pragma unroll
    for (int i = 0; i < 4; ++i)
        dstRel[i] = ((lr + 32 * i) * SA + lc) << 2;

    float acc[2][8][4];
#pragma unroll
    for (int mt = 0; mt < 2; ++mt)
#pragma unroll
        for (int nt = 0; nt < 8; ++nt)
#pragma unroll
            for (int i = 0; i < 4; ++i) acc[mt][nt][i] = 0.0f;

    const float* Arow = A + (size_t)(m0 + lr) * DD + lc;
    const float* Wrow = W + (size_t)(n0 + lr) * DD + lc;

    // prologue: stage 0
#pragma unroll
    for (int i = 0; i < 4; ++i) {
        cpa16(sbase + dstRel[i],              Arow + (size_t)32 * i * DD);
        cpa16(sbase + 2 * ABYTES + dstRel[i], Wrow + (size_t)32 * i * DD);
    }
    cp_commit();

    const int NT = DD / 32;   // 32
    for (int t = 0; t < NT; ++t) {
        const uint32_t soff = (uint32_t)(t & 1) * ABYTES;
        if (t + 1 < NT) {
            const uint32_t soff2 = (uint32_t)((t + 1) & 1) * ABYTES;
            const int k1 = (t + 1) * 32;
#pragma unroll
            for (int i = 0; i < 4; ++i) {
                cpa16(sbase + soff2 + dstRel[i],              Arow + (size_t)32 * i * DD + k1);
                cpa16(sbase + soff2 + 2 * ABYTES + dstRel[i], Wrow + (size_t)32 * i * DD + k1);
            }
            cp_commit();
            cp_wait<1>();
        } else {
            cp_wait<0>();
        }
        __syncthreads();

#pragma unroll
        for (int kk = 0; kk < 4; ++kk) {
            const uint32_t koff = kk * 32;
            uint32_t af[2][4], bf[4][4];
#pragma unroll
            for (int mt = 0; mt < 2; ++mt) ldsm_x4(af[mt], sbase + soff + aRel[mt] + koff);
#pragma unroll
            for (int p = 0; p < 4; ++p) ldsm_x4(bf[p], sbase + soff + bRel[p] + koff);
#pragma unroll
            for (int mt = 0; mt < 2; ++mt)
#pragma unroll
                for (int nt = 0; nt < 8; ++nt)
                    mma_tf32(acc[mt][nt], af[mt], &bf[nt >> 1][(nt & 1) * 2]);
        }
        __syncthreads();
    }

    // epilogue
#pragma unroll
    for (int mt = 0; mt < 2; ++mt) {
#pragma unroll
        for (int nt = 0; nt < 8; ++nt) {
            const int m1 = m0 + warp_m * 32 + mt * 16 + g;
            const int m2 = m1 + 8;
            const int n  = n0 + warp_n * 64 + nt * 8 + t4 * 2;
            if (QKV) {
                float2 lo = make_float2(__uint_as_float(f2tf32(acc[mt][nt][0])),
                                        __uint_as_float(f2tf32(acc[mt][nt][1])));
                float2 hi = make_float2(__uint_as_float(f2tf32(acc[mt][nt][2])),
                                        __uint_as_float(f2tf32(acc[mt][nt][3])));
                const int h = n / HDD, d = n % HDD;
                const int b1 = m1 / TT, t1 = m1 % TT;
                const int b2 = m2 / TT, t2 = m2 % TT;
                *(float2*)(dst + (((size_t)(b1 * HH + h) * TT + t1) * HDD + d)) = lo;
                *(float2*)(dst + (((size_t)(b2 * HH + h) * TT + t2) * HDD + d)) = hi;
            } else {
                float2 lo = make_float2(acc[mt][nt][0], acc[mt][nt][1]);
                float2 hi = make_float2(acc[mt][nt][2], acc[mt][nt][3]);
                *(float2*)(dst + (size_t)m1 * DD + n) = lo;
                *(float2*)(dst + (size_t)m2 * DD + n) = hi;
            }
        }
    }
}

__global__ void __launch_bounds__(256, 2)
gemm_qkv_kernel()
{
    const float* W = (blockIdx.z == 0) ? g_wqt : ((blockIdx.z == 1) ? g_wkt : g_wvt);
    float* dst     = (blockIdx.z == 0) ? g_q : ((blockIdx.z == 1) ? g_k : g_v);
    gemm_tc_body<1>(g_xt, W, dst);
}

__global__ void __launch_bounds__(256, 2)
gemm_out_kernel(float* __restrict__ out)
{
    gemm_tc_body<0>(g_att, g_wot, out);
}

// ---------------------------------------------------------------------------
// Tensor-core flash attention (tf32 MMA, fp32 softmax/accum, causal).
// CTA = (b, h, 128-row q tile), 8 warps, warp = 16 q rows, kv tiles of 64.
// K tile via cp.async; V transposed via LDG+STS (overlapped).
// ---------------------------------------------------------------------------
#define AS 68   // smem stride in words (16B-aligned rows)

__global__ void __launch_bounds__(256, 2) attn_kernel()
{
    extern __shared__ float sm[];
    float* Ps = sm;                 // 128 x AS : Q staging, then P tiles
    float* Ks = sm + 128 * AS;      // 64 x AS
    float* Vt = Ks + 64 * AS;       // 64 x AS  (rows = hd, cols = kv)

    const int tid  = threadIdx.x;
    const int lane = tid & 31;
    const int w    = tid >> 5;
    const int g    = lane >> 2;
    const int t4   = lane & 3;
    const int i8   = lane >> 3;
    const int rr   = lane & 7;

    const int qt = blockIdx.x;
    const int hh = blockIdx.y;
    const int bb = blockIdx.z;
    const int q0 = qt * 128;

    const size_t bh_off = (size_t)(bb * HH + hh) * TT * HDD;
    const float* Qg = g_q + bh_off;
    const float* Kg = g_k + bh_off;
    const float* Vg = g_v + bh_off;

    const uint32_t ksBase = sptr(Ks);

    // ---- load Q tile (128 x 64) ----
#pragma unroll
    for (int i = 0; i < 8; ++i) {
        int idx = tid + 256 * i;
        int r = idx >> 4, c = (idx & 15) << 2;
        *(float4*)&Ps[r * AS + c] = *(const float4*)&Qg[(size_t)(q0 + r) * HDD + c];
    }
    __syncthreads();

    // ---- Q fragments (register resident) ----
    uint32_t qf[8][4];
    {
        uint32_t qbase = sptr(Ps) +
            (((w * 16 + (i8 & 1) * 8 + rr) * AS + (i8 >> 1) * 4) << 2);
#pragma unroll
        for (int kk = 0; kk < 8; ++kk) ldsm_x4(qf[kk], qbase + kk * 32);
    }

    const uint32_t pbase = sptr(Ps) +
        (((w * 16 + (i8 & 1) * 8 + rr) * AS + (i8 >> 1) * 4) << 2);
    uint32_t kaddr[4], vaddr[4];
#pragma unroll
    for (int p = 0; p < 4; ++p) {
        kaddr[p] = sptr(Ks) + ((((2 * p + (i8 >> 1)) * 8 + rr) * AS + (i8 & 1) * 4) << 2);
        vaddr[p] = sptr(Vt) + ((((2 * p + (i8 >> 1)) * 8 + rr) * AS + (i8 & 1) * 4) << 2);
    }

    float oacc[8][4];
#pragma unroll
    for (int nt = 0; nt < 8; ++nt)
#pragma unroll
        for (int i = 0; i < 4; ++i) oacc[nt][i] = 0.0f;
    float mrow[2] = {-1e30f, -1e30f};
    float lrow[2] = {0.0f, 0.0f};

    const int wrow0 = q0 + w * 16;
    const int ktmax = 2 * qt + 1;

    for (int kt = 0; kt <= ktmax; ++kt) {
        __syncthreads();   // previous tile reads complete

        // ---- K tile via cp.async, V tile transposed via LDG+STS ----
#pragma unroll
        for (int i = 0; i < 4; ++i) {
            int idx = tid + 256 * i;
            int r = idx >> 4, c = (idx & 15) << 2;
            cpa16(ksBase + ((r * AS + c) << 2), &Kg[(size_t)(kt * 64 + r) * HDD + c]);
        }
#pragma unroll
        for (int i = 0; i < 4; ++i) {
            int idx = tid + 256 * i;
            int r = idx >> 4, c = (idx & 15) << 2;
            float4 v = *(const float4*)&Vg[(size_t)(kt * 64 + r) * HDD + c];
            Vt[(c + 0) * AS + r] = v.x;
            Vt[(c + 1) * AS + r] = v.y;
            Vt[(c + 2) * AS + r] = v.z;
            Vt[(c + 3) * AS + r] = v.w;
        }
        cp_commit();
        cp_wait<0>();
        __syncthreads();

        if (kt * 64 > wrow0 + 15) continue;   // tile fully masked for this warp

        // ---- S = Q K^T ----
        float sacc[8][4];
#pragma unroll
        for (int nt = 0; nt < 8; ++nt)
#pragma unroll
            for (int i = 0; i < 4; ++i) sacc[nt][i] = 0.0f;

#pragma unroll
        for (int kk = 0; kk < 8; ++kk) {
            uint32_t bf[4][4];
#pragma unroll
            for (int p = 0; p < 4; ++p) ldsm_x4(bf[p], kaddr[p] + kk * 32);
#pragma unroll
            for (int nt = 0; nt < 8; ++nt)
                mma_tf32(sacc[nt], qf[kk], &bf[nt >> 1][(nt & 1) * 2]);
        }

        // ---- scale + causal mask ----
        const int r0 = wrow0 + g;
        const int r1 = r0 + 8;
        if (kt * 64 + 63 > r0) {
#pragma unroll
            for (int nt = 0; nt < 8; ++nt) {
                const int c0 = kt * 64 + nt * 8 + 2 * t4;
                sacc[nt][0] = (c0     <= r0) ? sacc[nt][0] * 0.125f : -1e30f;
                sacc[nt][1] = (c0 + 1 <= r0) ? sacc[nt][1] * 0.125f : -1e30f;
                sacc[nt][2] = (c0     <= r1) ? sacc[nt][2] * 0.125f : -1e30f;
                sacc[nt][3] = (c0 + 1 <= r1) ? sacc[nt][3] * 0.125f : -1e30f;
            }
        } else {
#pragma unroll
            for (int nt = 0; nt < 8; ++nt)
#pragma unroll
                for (int i = 0; i < 4; ++i) sacc[nt][i] *= 0.125f;
        }

        // ---- online softmax ----
        float mx0 = -1e30f, mx1 = -1e30f;
#pragma unroll
        for (int nt = 0; nt < 8; ++nt) {
            mx0 = fmaxf(mx0, fmaxf(sacc[nt][0], sacc[nt][1]));
            mx1 = fmaxf(mx1, fmaxf(sacc[nt][2], sacc[nt][3]));
        }
        mx0 = fmaxf(mx0, __shfl_xor_sync(0xffffffffu, mx0, 1));
        mx0 = fmaxf(mx0, __shfl_xor_sync(0xffffffffu, mx0, 2));
        mx1 = fmaxf(mx1, __shfl_xor_sync(0xffffffffu, mx1, 1));
        mx1 = fmaxf(mx1, __shfl_xor_sync(0xffffffffu, mx1, 2));

        const float m0 = fmaxf(mrow[0], mx0);
        const float m1 = fmaxf(mrow[1], mx1);
        float rs0 = 0.0f, rs1 = 0.0f;
#pragma unroll
        for (int nt = 0; nt < 8; ++nt) {
            sacc[nt][0] = __expf(sacc[nt][0] - m0);
            sacc[nt][1] = __expf(sacc[nt][1] - m0);
            sacc[nt][2] = __expf(sacc[nt][2] - m1);
            sacc[nt][3] = __expf(sacc[nt][3] - m1);
            rs0 += sacc[nt][0] + sacc[nt][1];
            rs1 += sacc[nt][2] + sacc[nt][3];
        }
        rs0 += __shfl_xor_sync(0xffffffffu, rs0, 1);
        rs0 += __shfl_xor_sync(0xffffffffu, rs0, 2);
        rs1 += __shfl_xor_sync(0xffffffffu, rs1, 1);
        rs1 += __shfl_xor_sync(0xffffffffu, rs1, 2);

        const float a0 = __expf(mrow[0] - m0);
        const float a1 = __expf(mrow[1] - m1);
        lrow[0] = lrow[0] * a0 + rs0;  mrow[0] = m0;
        lrow[1] = lrow[1] * a1 + rs1;  mrow[1] = m1;
#pragma unroll
        for (int nt = 0; nt < 8; ++nt) {
            oacc[nt][0] *= a0; oacc[nt][1] *= a0;
            oacc[nt][2] *= a1; oacc[nt][3] *= a1;
        }

        // ---- write P tile (own warp's rows), tf32-rounded ----
        {
            uint32_t* Pu = (uint32_t*)Ps;
            const int lr0 = w * 16 + g;
#pragma unroll
            for (int nt = 0; nt < 8; ++nt) {
                const int co = nt * 8 + 2 * t4;
                uint2 lo = make_uint2(f2tf32(sacc[nt][0]), f2tf32(sacc[nt][1]));
                uint2 hi = make_uint2(f2tf32(sacc[nt][2]), f2tf32(sacc[nt][3]));
                *(uint2*)&Pu[lr0 * AS + co]       = lo;
                *(uint2*)&Pu[(lr0 + 8) * AS + co] = hi;
            }
        }
        __syncwarp();

        // ---- O += P V ----
#pragma unroll
        for (int kk = 0; kk < 8; ++kk) {
            uint32_t pf[4], bf[4][4];
            ldsm_x4(pf, pbase + kk * 32);
#pragma unroll
            for (int p = 0; p < 4; ++p) ldsm_x4(bf[p], vaddr[p] + kk * 32);
#pragma unroll
            for (int nt = 0; nt < 8; ++nt)
                mma_tf32(oacc[nt], pf, &bf[nt >> 1][(nt & 1) * 2]);
        }
    }

    // ---- epilogue (tf32-rounded for the out-projection cp.async path) ----
    const float inv0 = 1.0f / lrow[0];
    const float inv1 = 1.0f / lrow[1];
    const int row0 = wrow0 + g;
    const int row1 = row0 + 8;
#pragma unroll
    for (int nt = 0; nt < 8; ++nt) {
        const int col = hh * HDD + nt * 8 + 2 * t4;
        float2 lo = make_float2(__uint_as_float(f2tf32(oacc[nt][0] * inv0)),
                                __uint_as_float(f2tf32(oacc[nt][1] * inv0)));
        float2 hi = make_float2(__uint_as_float(f2tf32(oacc[nt][2] * inv1)),
                                __uint_as_float(f2tf32(oacc[nt][3] * inv1)));
        *(float2*)&g_att[((size_t)(bb * TT + row0)) * DD + col] = lo;
        *(float2*)&g_att[((size_t)(bb * TT + row1)) * DD + col] = hi;
    }
}

// ---------------------------------------------------------------------------
extern "C" void kernel_launch(void* const* d_in, const int* in_sizes, int n_in,
                              void* d_out, int out_size)
{
    const float* x  = (const float*)d_in[0];
    const float* wq = (const float*)d_in[1];
    const float* wk = (const float*)d_in[2];
    const float* wv = (const float*)d_in[3];
    const float* wo = (const float*)d_in[4];
    float* out = (float*)d_out;

    float* xt;  cudaGetSymbolAddress((void**)&xt,  g_xt);
    float* wqt; cudaGetSymbolAddress((void**)&wqt, g_wqt);
    float* wkt; cudaGetSymbolAddress((void**)&wkt, g_wkt);
    float* wvt; cudaGetSymbolAddress((void**)&wvt, g_wvt);
    float* wot; cudaGetSymbolAddress((void**)&wot, g_wot);

    const int ATT_SMEM = 256 * AS * (int)sizeof(float);   // 69632 B
    cudaFuncSetAttribute(attn_kernel,
                         cudaFuncAttributeMaxDynamicSharedMemorySize, ATT_SMEM);
    cudaFuncSetAttribute(gemm_qkv_kernel,
                         cudaFuncAttributeMaxDynamicSharedMemorySize, GEMM_SMEM);
    cudaFuncSetAttribute(gemm_out_kernel,
                         cudaFuncAttributeMaxDynamicSharedMemorySize, GEMM_SMEM);

    // 0) tf32 pre-rounding of x and weights
    tf32_round_kernel<<<(MROWS * DD / 4 + 255) / 256, 256>>>((const float4*)x,  (float4*)xt,  MROWS * DD / 4);
    tf32_round_kernel<<<(DD * DD / 4 + 255) / 256, 256>>>((const float4*)wq, (float4*)wqt, DD * DD / 4);
    tf32_round_kernel<<<(DD * DD / 4 + 255) / 256, 256>>>((const float4*)wk, (float4*)wkt, DD * DD / 4);
    tf32_round_kernel<<<(DD * DD / 4 + 255) / 256, 256>>>((const float4*)wv, (float4*)wvt, DD * DD / 4);
    tf32_round_kernel<<<(DD * DD / 4 + 255) / 256, 256>>>((const float4*)wo, (float4*)wot, DD * DD / 4);

    // 1) QKV projections (cp.async double-buffered tf32 MMA)
    dim3 gproj(DD / 128, MROWS / 128, 3);   // (8, 32, 3)
    gemm_qkv_kernel<<<gproj, 256, GEMM_SMEM>>>();

    // 2) causal flash attention
    dim3 gatt(TT / 128, HH, BB);            // (16, 16, 2)
    attn_kernel<<<gatt, 256, ATT_SMEM>>>();

    // 3) output projection
    dim3 gout(DD / 128, MROWS / 128, 1);    // (8, 32)
    gemm_out_kernel<<<gout, 256, GEMM_SMEM>>>(out);
}

// round 10
// speedup vs baseline: 1.1465x; 1.1465x over previous
#include <cuda_runtime.h>
#include <cuda_fp16.h>
#include <cstdint>

// Problem constants
#define BB   2
#define TT   2048
#define DD   1024
#define HH   16
#define HDD  64
#define MROWS (BB * TT)   // 4096

// Device scratch (no runtime allocation allowed)
__device__ __align__(16) float g_q[BB * HH * TT * HDD];     // [B,H,T,HD], tf32-rounded
__device__ __align__(16) float g_k[BB * HH * TT * HDD];
__device__ __align__(16) float g_v[BB * HH * TT * HDD];
__device__ __align__(16) float g_att[BB * TT * DD];         // [B,T,DIM], tf32-rounded

// ---------------------------------------------------------------------------
// helpers
// ---------------------------------------------------------------------------
__device__ __forceinline__ uint32_t f2tf32(float f) {
    uint32_t r;
    asm("cvt.rna.tf32.f32 %0, %1;" : "=r"(r) : "f"(f));
    return r;
}

__device__ __forceinline__ void mma_tf32(float* c, const uint32_t* a, const uint32_t* b) {
    asm volatile(
        "mma.sync.aligned.m16n8k8.row.col.f32.tf32.tf32.f32 "
        "{%0,%1,%2,%3}, {%4,%5,%6,%7}, {%8,%9}, {%0,%1,%2,%3};"
        : "+f"(c[0]), "+f"(c[1]), "+f"(c[2]), "+f"(c[3])
        : "r"(a[0]), "r"(a[1]), "r"(a[2]), "r"(a[3]), "r"(b[0]), "r"(b[1]));
}

__device__ __forceinline__ void mma_f16(float* c, const uint32_t* a,
                                        uint32_t b0, uint32_t b1) {
    asm volatile(
        "mma.sync.aligned.m16n8k16.row.col.f32.f16.f16.f32 "
        "{%0,%1,%2,%3}, {%4,%5,%6,%7}, {%8,%9}, {%0,%1,%2,%3};"
        : "+f"(c[0]), "+f"(c[1]), "+f"(c[2]), "+f"(c[3])
        : "r"(a[0]), "r"(a[1]), "r"(a[2]), "r"(a[3]), "r"(b0), "r"(b1));
}

__device__ __forceinline__ uint32_t sptr(const void* p) {
    return (uint32_t)__cvta_generic_to_shared(p);
}

__device__ __forceinline__ void ldsm_x4(uint32_t* r, uint32_t addr) {
    asm volatile("ldmatrix.sync.aligned.m8n8.x4.shared.b16 {%0,%1,%2,%3}, [%4];"
                 : "=r"(r[0]), "=r"(r[1]), "=r"(r[2]), "=r"(r[3]) : "r"(addr));
}

// ---------------------------------------------------------------------------
// fp16 NT GEMM: out[m,n] = sum_k A[m,k] * W[n,k]   (fp32 in/accum, fp16 MMA)
// R4 skeleton: CTA 128x128, BK=32, 256 threads, warp tile 32x64.
// Staging: LDG.128 fp32 -> cvt half2 -> STS.64; fragments via ldmatrix.x4.
// QKV==1: scatter tf32-rounded fp32 into [B,H,T,HD].
// ---------------------------------------------------------------------------
#define SAH 40   // halves per smem row (80 B, 16B-multiple, conflict-free ldsm)

template <int QKV>
__device__ __forceinline__ void gemm_f16_body(const float* __restrict__ A,
                                              const float* __restrict__ W,
                                              float* __restrict__ dst)
{
    __shared__ __align__(16) __half As[128 * SAH];
    __shared__ __align__(16) __half Bs[128 * SAH];

    const int tid    = threadIdx.x;
    const int lane   = tid & 31;
    const int wid    = tid >> 5;
    const int warp_m = wid & 3;
    const int warp_n = wid >> 2;
    const int g      = lane >> 2;
    const int t4     = lane & 3;
    const int i8     = lane >> 3;   // matrix index within ldmatrix.x4
    const int rr     = lane & 7;

    const int m0 = blockIdx.y * 128;
    const int n0 = blockIdx.x * 128;

    const int lr = tid >> 3;           // 0..31
    const int lc = (tid & 7) << 2;     // 0,4,...,28 (k position, floats/halves)

    // ldmatrix base addresses (bytes): rows * 80B + k-chunk
    uint32_t aAddr[2], bAddr[4];
#pragma unroll
    for (int mt = 0; mt < 2; ++mt)
        aAddr[mt] = sptr(As) +
            (uint32_t)((warp_m * 32 + mt * 16 + (i8 & 1) * 8 + rr) * (SAH * 2) + (i8 >> 1) * 16);
#pragma unroll
    for (int p = 0; p < 4; ++p)
        bAddr[p] = sptr(Bs) +
            (uint32_t)((warp_n * 64 + p * 16 + (i8 & 1) * 8 + rr) * (SAH * 2) + (i8 >> 1) * 16);

    float acc[2][8][4];
#pragma unroll
    for (int mt = 0; mt < 2; ++mt)
#pragma unroll
        for (int nt = 0; nt < 8; ++nt)
#pragma unroll
            for (int i = 0; i < 4; ++i) acc[mt][nt][i] = 0.0f;

    float4 areg[4], breg[4];
#pragma unroll
    for (int i = 0; i < 4; ++i) {
        areg[i] = *(const float4*)(A + (size_t)(m0 + lr + 32 * i) * DD + lc);
        breg[i] = *(const float4*)(W + (size_t)(n0 + lr + 32 * i) * DD + lc);
    }

    for (int k0 = 0; k0 < DD; k0 += 32) {
        // stage regs -> smem as half (packed 8-byte stores)
#pragma unroll
        for (int i = 0; i < 4; ++i) {
            const int r = lr + 32 * i;
            __half2 a01 = __floats2half2_rn(areg[i].x, areg[i].y);
            __half2 a23 = __floats2half2_rn(areg[i].z, areg[i].w);
            __half2 b01 = __floats2half2_rn(breg[i].x, breg[i].y);
            __half2 b23 = __floats2half2_rn(breg[i].z, breg[i].w);
            *(__half2*)&As[r * SAH + lc]     = a01;
            *(__half2*)&As[r * SAH + lc + 2] = a23;
            *(__half2*)&Bs[r * SAH + lc]     = b01;
            *(__half2*)&Bs[r * SAH + lc + 2] = b23;
        }
        __syncthreads();

        // prefetch next k-tile while the MMAs run
        if (k0 + 32 < DD) {
#pragma unroll
            for (int i = 0; i < 4; ++i) {
                areg[i] = *(const float4*)(A + (size_t)(m0 + lr + 32 * i) * DD + k0 + 32 + lc);
                breg[i] = *(const float4*)(W + (size_t)(n0 + lr + 32 * i) * DD + k0 + 32 + lc);
            }
        }

#pragma unroll
        for (int kk = 0; kk < 2; ++kk) {            // two k16 steps
            const uint32_t koff = kk * 32;           // 16 halves
            uint32_t af[2][4], bf[4][4];
#pragma unroll
            for (int mt = 0; mt < 2; ++mt) ldsm_x4(af[mt], aAddr[mt] + koff);
#pragma unroll
            for (int p = 0; p < 4; ++p) ldsm_x4(bf[p], bAddr[p] + koff);
#pragma unroll
            for (int mt = 0; mt < 2; ++mt)
#pragma unroll
                for (int nt = 0; nt < 8; ++nt)
                    mma_f16(acc[mt][nt], af[mt],
                            bf[nt >> 1][nt & 1], bf[nt >> 1][(nt & 1) + 2]);
        }
        __syncthreads();
    }

    // epilogue
#pragma unroll
    for (int mt = 0; mt < 2; ++mt) {
#pragma unroll
        for (int nt = 0; nt < 8; ++nt) {
            const int m1 = m0 + warp_m * 32 + mt * 16 + g;
            const int m2 = m1 + 8;
            const int n  = n0 + warp_n * 64 + nt * 8 + t4 * 2;
            if (QKV) {
                // round to tf32 so the tf32 attention consumes clean bits
                float2 lo = make_float2(__uint_as_float(f2tf32(acc[mt][nt][0])),
                                        __uint_as_float(f2tf32(acc[mt][nt][1])));
                float2 hi = make_float2(__uint_as_float(f2tf32(acc[mt][nt][2])),
                                        __uint_as_float(f2tf32(acc[mt][nt][3])));
                const int h = n / HDD, d = n % HDD;
                const int b1 = m1 / TT, t1 = m1 % TT;
                const int b2 = m2 / TT, t2 = m2 % TT;
                *(float2*)(dst + (((size_t)(b1 * HH + h) * TT + t1) * HDD + d)) = lo;
                *(float2*)(dst + (((size_t)(b2 * HH + h) * TT + t2) * HDD + d)) = hi;
            } else {
                float2 lo = make_float2(acc[mt][nt][0], acc[mt][nt][1]);
                float2 hi = make_float2(acc[mt][nt][2], acc[mt][nt][3]);
                *(float2*)(dst + (size_t)m1 * DD + n) = lo;
                *(float2*)(dst + (size_t)m2 * DD + n) = hi;
            }
        }
    }
}

__global__ void __launch_bounds__(256, 2)
gemm_qkv_kernel(const float* __restrict__ x,
                const float* __restrict__ wq,
                const float* __restrict__ wk,
                const float* __restrict__ wv)
{
    const float* W = (blockIdx.z == 0) ? wq : ((blockIdx.z == 1) ? wk : wv);
    float* dst     = (blockIdx.z == 0) ? g_q : ((blockIdx.z == 1) ? g_k : g_v);
    gemm_f16_body<1>(x, W, dst);
}

__global__ void __launch_bounds__(256, 2)
gemm_out_kernel(const float* __restrict__ wo, float* __restrict__ out)
{
    gemm_f16_body<0>(g_att, wo, out);
}

// ---------------------------------------------------------------------------
// Tensor-core flash attention (tf32 mma.sync, fp32 softmax/accum, causal).
// EXACT copy of the R4 passing version + reversed qt order (tail balance).
// CTA = (b, h, 128-row q tile), 8 warps, warp = 16 q rows, kv tiles of 64.
// ---------------------------------------------------------------------------
#define AS 68   // smem stride in words (16B-aligned rows)

__global__ void __launch_bounds__(256, 2) attn_kernel()
{
    extern __shared__ float sm[];
    float* Ps = sm;                 // 128 x AS : Q staging, then P tiles
    float* Ks = sm + 128 * AS;      // 64 x AS
    float* Vt = Ks + 64 * AS;       // 64 x AS  (rows = hd, cols = kv)

    const int tid  = threadIdx.x;
    const int lane = tid & 31;
    const int w    = tid >> 5;
    const int g    = lane >> 2;
    const int t4   = lane & 3;
    const int i8   = lane >> 3;
    const int rr   = lane & 7;

    const int qt = (int)gridDim.x - 1 - (int)blockIdx.x;   // heavy tiles first
    const int hh = blockIdx.y;
    const int bb = blockIdx.z;
    const int q0 = qt * 128;

    const size_t bh_off = (size_t)(bb * HH + hh) * TT * HDD;
    const float* Qg = g_q + bh_off;
    const float* Kg = g_k + bh_off;
    const float* Vg = g_v + bh_off;

    // ---- load Q tile (128 x 64) ----
#pragma unroll
    for (int i = 0; i < 8; ++i) {
        int idx = tid + 256 * i;
        int r = idx >> 4, c = (idx & 15) << 2;
        *(float4*)&Ps[r * AS + c] = *(const float4*)&Qg[(size_t)(q0 + r) * HDD + c];
    }
    __syncthreads();

    // ---- Q fragments (register resident for whole kv loop) ----
    uint32_t qf[8][4];
    {
        uint32_t qbase = sptr(Ps) +
            (((w * 16 + (i8 & 1) * 8 + rr) * AS + (i8 >> 1) * 4) << 2);
#pragma unroll
        for (int kk = 0; kk < 8; ++kk) ldsm_x4(qf[kk], qbase + kk * 32);
    }

    const uint32_t pbase = sptr(Ps) +
        (((w * 16 + (i8 & 1) * 8 + rr) * AS + (i8 >> 1) * 4) << 2);
    uint32_t kaddr[4], vaddr[4];
#pragma unroll
    for (int p = 0; p < 4; ++p) {
        kaddr[p] = sptr(Ks) + ((((2 * p + (i8 >> 1)) * 8 + rr) * AS + (i8 & 1) * 4) << 2);
        vaddr[p] = sptr(Vt) + ((((2 * p + (i8 >> 1)) * 8 + rr) * AS + (i8 & 1) * 4) << 2);
    }

    float oacc[8][4];
#pragma unroll
    for (int nt = 0; nt < 8; ++nt)
#pragma unroll
        for (int i = 0; i < 4; ++i) oacc[nt][i] = 0.0f;
    float mrow[2] = {-1e30f, -1e30f};
    float lrow[2] = {0.0f, 0.0f};

    const int wrow0 = q0 + w * 16;
    const int ktmax = 2 * qt + 1;

    for (int kt = 0; kt <= ktmax; ++kt) {
        __syncthreads();   // previous tile reads complete

        // ---- load K tile and transposed V tile ----
#pragma unroll
        for (int i = 0; i < 4; ++i) {
            int idx = tid + 256 * i;
            int r = idx >> 4, c = (idx & 15) << 2;
            *(float4*)&Ks[r * AS + c] = *(const float4*)&Kg[(size_t)(kt * 64 + r) * HDD + c];
            float4 v = *(const float4*)&Vg[(size_t)(kt * 64 + r) * HDD + c];
            Vt[(c + 0) * AS + r] = v.x;
            Vt[(c + 1) * AS + r] = v.y;
            Vt[(c + 2) * AS + r] = v.z;
            Vt[(c + 3) * AS + r] = v.w;
        }
        __syncthreads();

        if (kt * 64 > wrow0 + 15) continue;   // tile fully masked for this warp

        // ---- S = Q K^T (16 x 64 per warp) ----
        float sacc[8][4];
#pragma unroll
        for (int nt = 0; nt < 8; ++nt)
#pragma unroll
            for (int i = 0; i < 4; ++i) sacc[nt][i] = 0.0f;

#pragma unroll
        for (int kk = 0; kk < 8; ++kk) {
            uint32_t bf[4][4];
#pragma unroll
            for (int p = 0; p < 4; ++p) ldsm_x4(bf[p], kaddr[p] + kk * 32);
#pragma unroll
            for (int nt = 0; nt < 8; ++nt)
                mma_tf32(sacc[nt], qf[kk], &bf[nt >> 1][(nt & 1) * 2]);
        }

        // ---- scale + causal mask ----
        const int r0 = wrow0 + g;
        const int r1 = r0 + 8;
        if (kt * 64 + 63 > r0) {
#pragma unroll
            for (int nt = 0; nt < 8; ++nt) {
                const int c0 = kt * 64 + nt * 8 + 2 * t4;
                sacc[nt][0] = (c0     <= r0) ? sacc[nt][0] * 0.125f : -1e30f;
                sacc[nt][1] = (c0 + 1 <= r0) ? sacc[nt][1] * 0.125f : -1e30f;
                sacc[nt][2] = (c0     <= r1) ? sacc[nt][2] * 0.125f : -1e30f;
                sacc[nt][3] = (c0 + 1 <= r1) ? sacc[nt][3] * 0.125f : -1e30f;
            }
        } else {
#pragma unroll
            for (int nt = 0; nt < 8; ++nt)
#pragma unroll
                for (int i = 0; i < 4; ++i) sacc[nt][i] *= 0.125f;
        }

        // ---- online softmax (two rows per thread, reduce over 4 t4 lanes) ----
        float mx0 = -1e30f, mx1 = -1e30f;
#pragma unroll
        for (int nt = 0; nt < 8; ++nt) {
            mx0 = fmaxf(mx0, fmaxf(sacc[nt][0], sacc[nt][1]));
            mx1 = fmaxf(mx1, fmaxf(sacc[nt][2], sacc[nt][3]));
        }
        mx0 = fmaxf(mx0, __shfl_xor_sync(0xffffffffu, mx0, 1));
        mx0 = fmaxf(mx0, __shfl_xor_sync(0xffffffffu, mx0, 2));
        mx1 = fmaxf(mx1, __shfl_xor_sync(0xffffffffu, mx1, 1));
        mx1 = fmaxf(mx1, __shfl_xor_sync(0xffffffffu, mx1, 2));

        const float m0 = fmaxf(mrow[0], mx0);
        const float m1 = fmaxf(mrow[1], mx1);
        float rs0 = 0.0f, rs1 = 0.0f;
#pragma unroll
        for (int nt = 0; nt < 8; ++nt) {
            sacc[nt][0] = __expf(sacc[nt][0] - m0);
            sacc[nt][1] = __expf(sacc[nt][1] - m0);
            sacc[nt][2] = __expf(sacc[nt][2] - m1);
            sacc[nt][3] = __expf(sacc[nt][3] - m1);
            rs0 += sacc[nt][0] + sacc[nt][1];
            rs1 += sacc[nt][2] + sacc[nt][3];
        }
        rs0 += __shfl_xor_sync(0xffffffffu, rs0, 1);
        rs0 += __shfl_xor_sync(0xffffffffu, rs0, 2);
        rs1 += __shfl_xor_sync(0xffffffffu, rs1, 1);
        rs1 += __shfl_xor_sync(0xffffffffu, rs1, 2);

        const float a0 = __expf(mrow[0] - m0);
        const float a1 = __expf(mrow[1] - m1);
        lrow[0] = lrow[0] * a0 + rs0;  mrow[0] = m0;
        lrow[1] = lrow[1] * a1 + rs1;  mrow[1] = m1;
#pragma unroll
        for (int nt = 0; nt < 8; ++nt) {
            oacc[nt][0] *= a0; oacc[nt][1] *= a0;
            oacc[nt][2] *= a1; oacc[nt][3] *= a1;
        }

        // ---- write P tile (own warp's 16 rows only), tf32-rounded ----
        {
            uint32_t* Pu = (uint32_t*)Ps;
            const int lr0 = w * 16 + g;
#pragma unroll
            for (int nt = 0; nt < 8; ++nt) {
                const int co = nt * 8 + 2 * t4;
                uint2 lo = make_uint2(f2tf32(sacc[nt][0]), f2tf32(sacc[nt][1]));
                uint2 hi = make_uint2(f2tf32(sacc[nt][2]), f2tf32(sacc[nt][3]));
                *(uint2*)&Pu[lr0 * AS + co]       = lo;
                *(uint2*)&Pu[(lr0 + 8) * AS + co] = hi;
            }
        }
        __syncwarp();

        // ---- O += P V ----
#pragma unroll
        for (int kk = 0; kk < 8; ++kk) {
            uint32_t pf[4], bf[4][4];
            ldsm_x4(pf, pbase + kk * 32);
#pragma unroll
            for (int p = 0; p < 4; ++p) ldsm_x4(bf[p], vaddr[p] + kk * 32);
#pragma unroll
            for (int nt = 0; nt < 8; ++nt)
                mma_tf32(oacc[nt], pf, &bf[nt >> 1][(nt & 1) * 2]);
        }
    }

    // ---- epilogue ----
    const float inv0 = 1.0f / lrow[0];
    const float inv1 = 1.0f / lrow[1];
    const int row0 = wrow0 + g;
    const int row1 = row0 + 8;
#pragma unroll
    for (int nt = 0; nt < 8; ++nt) {
        const int col = hh * HDD + nt * 8 + 2 * t4;
        float2 lo = make_float2(oacc[nt][0] * inv0, oacc[nt][1] * inv0);
        float2 hi = make_float2(oacc[nt][2] * inv1, oacc[nt][3] * inv1);
        *(float2*)&g_att[((size_t)(bb * TT + row0)) * DD + col] = lo;
        *(float2*)&g_att[((size_t)(bb * TT + row1)) * DD + col] = hi;
    }
}

// ---------------------------------------------------------------------------
extern "C" void kernel_launch(void* const* d_in, const int* in_sizes, int n_in,
                              void* d_out, int out_size)
{
    const float* x  = (const float*)d_in[0];
    const float* wq = (const float*)d_in[1];
    const float* wk = (const float*)d_in[2];
    const float* wv = (const float*)d_in[3];
    const float* wo = (const float*)d_in[4];
    float* out = (float*)d_out;

    const int ATT_SMEM = 256 * AS * (int)sizeof(float);   // 69632 B
    cudaFuncSetAttribute(attn_kernel,
                         cudaFuncAttributeMaxDynamicSharedMemorySize, ATT_SMEM);

    // 1) QKV projections (fp16 m16n8k16 tensor cores)
    dim3 gproj(DD / 128, MROWS / 128, 3);   // (8, 32, 3)
    gemm_qkv_kernel<<<gproj, 256>>>(x, wq, wk, wv);

    // 2) causal flash attention (tf32 tensor cores, proven)
    dim3 gatt(TT / 128, HH, BB);            // (16, 16, 2)
    attn_kernel<<<gatt, 256, ATT_SMEM>>>();

    // 3) output projection (fp16 tensor cores)
    dim3 gout(DD / 128, MROWS / 128, 1);    // (8, 32)
    gemm_out_kernel<<<gout, 256>>>(wo, out);
}

// round 11
// speedup vs baseline: 1.4527x; 1.2671x over previous
#include <cuda_runtime.h>
#include <cuda_fp16.h>
#include <cstdint>

// Problem constants
#define BB   2
#define TT   2048
#define DD   1024
#define HH   16
#define HDD  64
#define MROWS (BB * TT)   // 4096

// Device scratch (no runtime allocation allowed)
__device__ __align__(16) __half g_qh[BB * HH * TT * HDD];   // [B,H,T,HD] fp16
__device__ __align__(16) __half g_kh[BB * HH * TT * HDD];
__device__ __align__(16) __half g_vh[BB * HH * TT * HDD];
__device__ __align__(16) float  g_att[BB * TT * DD];        // [B,T,DIM] fp32

// ---------------------------------------------------------------------------
// helpers
// ---------------------------------------------------------------------------
__device__ __forceinline__ void mma_f16(float* c, const uint32_t* a,
                                        uint32_t b0, uint32_t b1) {
    asm volatile(
        "mma.sync.aligned.m16n8k16.row.col.f32.f16.f16.f32 "
        "{%0,%1,%2,%3}, {%4,%5,%6,%7}, {%8,%9}, {%0,%1,%2,%3};"
        : "+f"(c[0]), "+f"(c[1]), "+f"(c[2]), "+f"(c[3])
        : "r"(a[0]), "r"(a[1]), "r"(a[2]), "r"(a[3]), "r"(b0), "r"(b1));
}

__device__ __forceinline__ uint32_t sptr(const void* p) {
    return (uint32_t)__cvta_generic_to_shared(p);
}

__device__ __forceinline__ void ldsm_x4(uint32_t* r, uint32_t addr) {
    asm volatile("ldmatrix.sync.aligned.m8n8.x4.shared.b16 {%0,%1,%2,%3}, [%4];"
                 : "=r"(r[0]), "=r"(r[1]), "=r"(r[2]), "=r"(r[3]) : "r"(addr));
}

// ---------------------------------------------------------------------------
// fp16 NT GEMM: out[m,n] = sum_k A[m,k] * W[n,k]   (fp32 in/accum, fp16 MMA)
// PROVEN (R8): CTA 128x128, BK=32, 256 threads, warp tile 32x64.
// QKV==1: write fp16 into [B,H,T,HD]; else fp32 to dst.
// ---------------------------------------------------------------------------
#define SAH 40   // halves per smem row (80 B)

template <int QKV>
__device__ __forceinline__ void gemm_f16_body(const float* __restrict__ A,
                                              const float* __restrict__ W,
                                              void* __restrict__ dstp)
{
    __shared__ __align__(16) __half As[128 * SAH];
    __shared__ __align__(16) __half Bs[128 * SAH];

    const int tid    = threadIdx.x;
    const int lane   = tid & 31;
    const int wid    = tid >> 5;
    const int warp_m = wid & 3;
    const int warp_n = wid >> 2;
    const int g      = lane >> 2;
    const int t4     = lane & 3;
    const int i8     = lane >> 3;
    const int rr     = lane & 7;

    const int m0 = blockIdx.y * 128;
    const int n0 = blockIdx.x * 128;

    const int lr = tid >> 3;
    const int lc = (tid & 7) << 2;

    uint32_t aAddr[2], bAddr[4];
#pragma unroll
    for (int mt = 0; mt < 2; ++mt)
        aAddr[mt] = sptr(As) +
            (uint32_t)((warp_m * 32 + mt * 16 + (i8 & 1) * 8 + rr) * (SAH * 2) + (i8 >> 1) * 16);
#pragma unroll
    for (int p = 0; p < 4; ++p)
        bAddr[p] = sptr(Bs) +
            (uint32_t)((warp_n * 64 + p * 16 + (i8 & 1) * 8 + rr) * (SAH * 2) + (i8 >> 1) * 16);

    float acc[2][8][4];
#pragma unroll
    for (int mt = 0; mt < 2; ++mt)
#pragma unroll
        for (int nt = 0; nt < 8; ++nt)
#pragma unroll
            for (int i = 0; i < 4; ++i) acc[mt][nt][i] = 0.0f;

    float4 areg[4], breg[4];
#pragma unroll
    for (int i = 0; i < 4; ++i) {
        areg[i] = *(const float4*)(A + (size_t)(m0 + lr + 32 * i) * DD + lc);
        breg[i] = *(const float4*)(W + (size_t)(n0 + lr + 32 * i) * DD + lc);
    }

    for (int k0 = 0; k0 < DD; k0 += 32) {
#pragma unroll
        for (int i = 0; i < 4; ++i) {
            const int r = lr + 32 * i;
            *(__half2*)&As[r * SAH + lc]     = __floats2half2_rn(areg[i].x, areg[i].y);
            *(__half2*)&As[r * SAH + lc + 2] = __floats2half2_rn(areg[i].z, areg[i].w);
            *(__half2*)&Bs[r * SAH + lc]     = __floats2half2_rn(breg[i].x, breg[i].y);
            *(__half2*)&Bs[r * SAH + lc + 2] = __floats2half2_rn(breg[i].z, breg[i].w);
        }
        __syncthreads();

        if (k0 + 32 < DD) {
#pragma unroll
            for (int i = 0; i < 4; ++i) {
                areg[i] = *(const float4*)(A + (size_t)(m0 + lr + 32 * i) * DD + k0 + 32 + lc);
                breg[i] = *(const float4*)(W + (size_t)(n0 + lr + 32 * i) * DD + k0 + 32 + lc);
            }
        }

#pragma unroll
        for (int kk = 0; kk < 2; ++kk) {
            const uint32_t koff = kk * 32;
            uint32_t af[2][4], bf[4][4];
#pragma unroll
            for (int mt = 0; mt < 2; ++mt) ldsm_x4(af[mt], aAddr[mt] + koff);
#pragma unroll
            for (int p = 0; p < 4; ++p) ldsm_x4(bf[p], bAddr[p] + koff);
#pragma unroll
            for (int mt = 0; mt < 2; ++mt)
#pragma unroll
                for (int nt = 0; nt < 8; ++nt)
                    mma_f16(acc[mt][nt], af[mt],
                            bf[nt >> 1][nt & 1], bf[nt >> 1][(nt & 1) + 2]);
        }
        __syncthreads();
    }

#pragma unroll
    for (int mt = 0; mt < 2; ++mt) {
#pragma unroll
        for (int nt = 0; nt < 8; ++nt) {
            const int m1 = m0 + warp_m * 32 + mt * 16 + g;
            const int m2 = m1 + 8;
            const int n  = n0 + warp_n * 64 + nt * 8 + t4 * 2;
            if (QKV) {
                __half* dst = (__half*)dstp;
                const int h = n / HDD, d = n % HDD;
                const int b1 = m1 / TT, t1 = m1 % TT;
                const int b2 = m2 / TT, t2 = m2 % TT;
                *(__half2*)(dst + (((size_t)(b1 * HH + h) * TT + t1) * HDD + d)) =
                    __floats2half2_rn(acc[mt][nt][0], acc[mt][nt][1]);
                *(__half2*)(dst + (((size_t)(b2 * HH + h) * TT + t2) * HDD + d)) =
                    __floats2half2_rn(acc[mt][nt][2], acc[mt][nt][3]);
            } else {
                float* dst = (float*)dstp;
                *(float2*)(dst + (size_t)m1 * DD + n) = make_float2(acc[mt][nt][0], acc[mt][nt][1]);
                *(float2*)(dst + (size_t)m2 * DD + n) = make_float2(acc[mt][nt][2], acc[mt][nt][3]);
            }
        }
    }
}

__global__ void __launch_bounds__(256, 2)
gemm_qkv_kernel(const float* __restrict__ x,
                const float* __restrict__ wq,
                const float* __restrict__ wk,
                const float* __restrict__ wv)
{
    const float* W = (blockIdx.z == 0) ? wq : ((blockIdx.z == 1) ? wk : wv);
    __half* dst    = (blockIdx.z == 0) ? g_qh : ((blockIdx.z == 1) ? g_kh : g_vh);
    gemm_f16_body<1>(x, W, dst);
}

__global__ void __launch_bounds__(256, 2)
gemm_out_kernel(const float* __restrict__ wo, float* __restrict__ out)
{
    gemm_f16_body<0>(g_att, wo, out);
}

// ---------------------------------------------------------------------------
// fp16 tensor-core flash attention (fp32 softmax/accum, causal).
// R4 skeleton + proven fp16 fragment mapping. CTA = (b,h,128 q rows),
// 8 warps x 16 rows, kv tiles of 64. V transposed via scalar STS (proven).
// ---------------------------------------------------------------------------
#define ARH 72    // halves per attention smem row (144 B, 16B-multiple)

__global__ void __launch_bounds__(256, 2) attn_kernel()
{
    __shared__ __align__(16) __half sQ[128 * ARH];   // Q staging, then P tiles
    __shared__ __align__(16) __half sK[64 * ARH];
    __shared__ __align__(16) __half sVt[64 * ARH];   // rows = hd, cols = kv

    const int tid  = threadIdx.x;
    const int lane = tid & 31;
    const int w    = tid >> 5;
    const int g    = lane >> 2;
    const int t4   = lane & 3;
    const int i8   = lane >> 3;
    const int rr   = lane & 7;

    const int qt = (int)gridDim.x - 1 - (int)blockIdx.x;   // heavy tiles first
    const int hh = blockIdx.y;
    const int bb = blockIdx.z;
    const int q0 = qt * 128;

    const size_t bh_off = (size_t)(bb * HH + hh) * TT * HDD;
    const __half* Qg = g_qh + bh_off;
    const __half* Kg = g_kh + bh_off;
    const __half* Vg = g_vh + bh_off;

    // ---- load Q tile (128 x 64 halves) ----
#pragma unroll
    for (int i = 0; i < 4; ++i) {
        int idx = tid + 256 * i;               // 1024 chunks of 8 halves
        int r = idx >> 3, c = (idx & 7) << 3;
        *(uint4*)(sQ + r * ARH + c) = *(const uint4*)(Qg + (size_t)(q0 + r) * HDD + c);
    }
    __syncthreads();

    // ---- Q fragments (register resident; 4 k16 steps over hd=64) ----
    uint32_t qf[4][4];
    const uint32_t pRel = (uint32_t)((w * 16 + (i8 & 1) * 8 + rr) * (ARH * 2) + (i8 >> 1) * 16);
    {
        const uint32_t qb = sptr(sQ) + pRel;
#pragma unroll
        for (int kk = 0; kk < 4; ++kk) ldsm_x4(qf[kk], qb + kk * 32);
    }

    uint32_t kAddr[4], vAddr[4];
#pragma unroll
    for (int p = 0; p < 4; ++p) {
        const uint32_t rel = (uint32_t)((p * 16 + (i8 & 1) * 8 + rr) * (ARH * 2) + (i8 >> 1) * 16);
        kAddr[p] = sptr(sK) + rel;
        vAddr[p] = sptr(sVt) + rel;
    }

    float oacc[8][4];
#pragma unroll
    for (int nt = 0; nt < 8; ++nt)
#pragma unroll
        for (int i = 0; i < 4; ++i) oacc[nt][i] = 0.0f;
    float mrow[2] = {-1e30f, -1e30f};
    float lrow[2] = {0.0f, 0.0f};

    const int wrow0 = q0 + w * 16;
    const int ktmax = 2 * qt + 1;

    for (int kt = 0; kt <= ktmax; ++kt) {
        __syncthreads();   // previous tile reads complete

        // ---- load K tile; V tile transposed via scalar stores ----
#pragma unroll
        for (int i = 0; i < 2; ++i) {
            int idx = tid + 256 * i;           // 512 chunks of 8 halves
            int r = idx >> 3, c = (idx & 7) << 3;
            *(uint4*)(sK + r * ARH + c) = *(const uint4*)(Kg + (size_t)(kt * 64 + r) * HDD + c);
            uint4 vv = *(const uint4*)(Vg + (size_t)(kt * 64 + r) * HDD + c);
            const __half* vh = (const __half*)&vv;
#pragma unroll
            for (int j = 0; j < 8; ++j) sVt[(c + j) * ARH + r] = vh[j];
        }
        __syncthreads();

        if (kt * 64 > wrow0 + 15) continue;    // tile fully masked for this warp

        // ---- S = Q K^T (16 x 64 per warp) ----
        float sacc[8][4];
#pragma unroll
        for (int nt = 0; nt < 8; ++nt)
#pragma unroll
            for (int i = 0; i < 4; ++i) sacc[nt][i] = 0.0f;

#pragma unroll
        for (int kk = 0; kk < 4; ++kk) {
            uint32_t bf[4][4];
#pragma unroll
            for (int p = 0; p < 4; ++p) ldsm_x4(bf[p], kAddr[p] + kk * 32);
#pragma unroll
            for (int nt = 0; nt < 8; ++nt)
                mma_f16(sacc[nt], qf[kk],
                        bf[nt >> 1][nt & 1], bf[nt >> 1][(nt & 1) + 2]);
        }

        // ---- scale + causal mask ----
        const int r0 = wrow0 + g;
        const int r1 = r0 + 8;
        if (kt * 64 + 63 > r0) {
#pragma unroll
            for (int nt = 0; nt < 8; ++nt) {
                const int c0 = kt * 64 + nt * 8 + 2 * t4;
                sacc[nt][0] = (c0     <= r0) ? sacc[nt][0] * 0.125f : -1e30f;
                sacc[nt][1] = (c0 + 1 <= r0) ? sacc[nt][1] * 0.125f : -1e30f;
                sacc[nt][2] = (c0     <= r1) ? sacc[nt][2] * 0.125f : -1e30f;
                sacc[nt][3] = (c0 + 1 <= r1) ? sacc[nt][3] * 0.125f : -1e30f;
            }
        } else {
#pragma unroll
            for (int nt = 0; nt < 8; ++nt)
#pragma unroll
                for (int i = 0; i < 4; ++i) sacc[nt][i] *= 0.125f;
        }

        // ---- online softmax (two rows per thread, reduce over 4 t4 lanes) ----
        float mx0 = -1e30f, mx1 = -1e30f;
#pragma unroll
        for (int nt = 0; nt < 8; ++nt) {
            mx0 = fmaxf(mx0, fmaxf(sacc[nt][0], sacc[nt][1]));
            mx1 = fmaxf(mx1, fmaxf(sacc[nt][2], sacc[nt][3]));
        }
        mx0 = fmaxf(mx0, __shfl_xor_sync(0xffffffffu, mx0, 1));
        mx0 = fmaxf(mx0, __shfl_xor_sync(0xffffffffu, mx0, 2));
        mx1 = fmaxf(mx1, __shfl_xor_sync(0xffffffffu, mx1, 1));
        mx1 = fmaxf(mx1, __shfl_xor_sync(0xffffffffu, mx1, 2));

        const float m0 = fmaxf(mrow[0], mx0);
        const float m1 = fmaxf(mrow[1], mx1);
        float rs0 = 0.0f, rs1 = 0.0f;
#pragma unroll
        for (int nt = 0; nt < 8; ++nt) {
            sacc[nt][0] = __expf(sacc[nt][0] - m0);
            sacc[nt][1] = __expf(sacc[nt][1] - m0);
            sacc[nt][2] = __expf(sacc[nt][2] - m1);
            sacc[nt][3] = __expf(sacc[nt][3] - m1);
            rs0 += sacc[nt][0] + sacc[nt][1];
            rs1 += sacc[nt][2] + sacc[nt][3];
        }
        rs0 += __shfl_xor_sync(0xffffffffu, rs0, 1);
        rs0 += __shfl_xor_sync(0xffffffffu, rs0, 2);
        rs1 += __shfl_xor_sync(0xffffffffu, rs1, 1);
        rs1 += __shfl_xor_sync(0xffffffffu, rs1, 2);

        const float a0 = __expf(mrow[0] - m0);
        const float a1 = __expf(mrow[1] - m1);
        lrow[0] = lrow[0] * a0 + rs0;  mrow[0] = m0;
        lrow[1] = lrow[1] * a1 + rs1;  mrow[1] = m1;
#pragma unroll
        for (int nt = 0; nt < 8; ++nt) {
            oacc[nt][0] *= a0; oacc[nt][1] *= a0;
            oacc[nt][2] *= a1; oacc[nt][3] *= a1;
        }

        // ---- write P tile (own warp's 16 rows only), fp16 ----
        {
            const int lr0 = w * 16 + g;
#pragma unroll
            for (int nt = 0; nt < 8; ++nt) {
                const int co = nt * 8 + 2 * t4;
                *(__half2*)&sQ[lr0 * ARH + co]       = __floats2half2_rn(sacc[nt][0], sacc[nt][1]);
                *(__half2*)&sQ[(lr0 + 8) * ARH + co] = __floats2half2_rn(sacc[nt][2], sacc[nt][3]);
            }
        }
        __syncwarp();

        // ---- O += P V  (B = sVt rows of hd) ----
#pragma unroll
        for (int kk = 0; kk < 4; ++kk) {
            uint32_t pf[4], vf[4][4];
            ldsm_x4(pf, sptr(sQ) + pRel + kk * 32);
#pragma unroll
            for (int p = 0; p < 4; ++p) ldsm_x4(vf[p], vAddr[p] + kk * 32);
#pragma unroll
            for (int nt = 0; nt < 8; ++nt)
                mma_f16(oacc[nt], pf,
                        vf[nt >> 1][nt & 1], vf[nt >> 1][(nt & 1) + 2]);
        }
    }

    // ---- epilogue: normalize, fp32 into g_att [B,T,DIM] ----
    const float inv0 = 1.0f / lrow[0];
    const float inv1 = 1.0f / lrow[1];
    const int row0 = wrow0 + g;
    const int row1 = row0 + 8;
#pragma unroll
    for (int nt = 0; nt < 8; ++nt) {
        const int col = hh * HDD + nt * 8 + 2 * t4;
        *(float2*)&g_att[((size_t)(bb * TT + row0)) * DD + col] =
            make_float2(oacc[nt][0] * inv0, oacc[nt][1] * inv0);
        *(float2*)&g_att[((size_t)(bb * TT + row1)) * DD + col] =
            make_float2(oacc[nt][2] * inv1, oacc[nt][3] * inv1);
    }
}

// ---------------------------------------------------------------------------
extern "C" void kernel_launch(void* const* d_in, const int* in_sizes, int n_in,
                              void* d_out, int out_size)
{
    const float* x  = (const float*)d_in[0];
    const float* wq = (const float*)d_in[1];
    const float* wk = (const float*)d_in[2];
    const float* wv = (const float*)d_in[3];
    const float* wo = (const float*)d_in[4];
    float* out = (float*)d_out;

    // 1) QKV projections (fp16 m16n8k16, proven)
    dim3 gproj(DD / 128, MROWS / 128, 3);   // (8, 32, 3)
    gemm_qkv_kernel<<<gproj, 256>>>(x, wq, wk, wv);

    // 2) causal flash attention (fp16 tensor cores)
    dim3 gatt(TT / 128, HH, BB);            // (16, 16, 2)
    attn_kernel<<<gatt, 256>>>();

    // 3) output projection (fp16 tensor cores, fp32 result)
    dim3 gout(DD / 128, MROWS / 128, 1);    // (8, 32)
    gemm_out_kernel<<<gout, 256>>>(wo, out);
}